// round 15
// baseline (speedup 1.0000x reference)
#include <cuda_runtime.h>
#include <cstdint>

// ---------------- problem constants ----------------
#define NPIX   65536            // 256*256
#define LOf    (-3.0f)
#define Hstep  (6.0f / 63.0f)   // linspace(-3,3,64) spacing
#define A2     (4.0e-4f)        // FALL_OFF^2
#define EPSf   (1e-6f)
#define SCALE  64.0f            // fp16 range management; cancels in normalization

// ---------------- tiling ---------------------------
#define NIB    16               // (img,batch): 2*8
#define NCH    128              // chunks per (img,batch)
#define KPIX   512              // pixels per block
#define SPX    64               // pixels per stage (mma K-window)
#define NSTG   (KPIX / SPX)     // 8
#define NBLK   (NIB * NCH)      // 2048

// SMEM layout (dynamic, 57344 B):
//   [0, 8192):  s1,s2,s3,siy  (4 x 512 f32)
//   [8192 + buf*24576 + j*8192): W_j stage matrix, 64 bins x 64 px fp16,
//       128 B rows, SW128 xor-swizzle ((row&7)<<4)
#define SMEM_SZ   57344
#define W_OFF     8192
#define W_BUFSTR  24576

// ---------------- static scratch -------------------
__device__ float g_partial[NBLK][3 * 4096];   // ~100 MB
__device__ float g_hist[NIB][3 * 4096];
__device__ float g_hb[8];

// ---------------- helpers --------------------------
__device__ __forceinline__ uint32_t smem_u32(const void* p) {
    uint32_t a;
    asm("{ .reg .u64 t; cvta.to.shared.u64 t, %1; cvt.u32.u64 %0, t; }" : "=r"(a) : "l"(p));
    return a;
}
__device__ __forceinline__ float frcp(float q) {
    float r;
    asm("rcp.approx.f32 %0, %1;" : "=f"(r) : "f"(q));
    return r;
}
#define STS64(addr, v0, v1) \
    asm volatile("st.shared.v2.b32 [%0], {%1,%2};" :: "r"(addr), "r"(v0), "r"(v1) : "memory")

#define LDSM4(r0, r1, r2, r3, addr) \
    asm volatile("ldmatrix.sync.aligned.m8n8.x4.shared.b16 {%0,%1,%2,%3}, [%4];" \
        : "=r"(r0), "=r"(r1), "=r"(r2), "=r"(r3) : "r"(addr))

#define MMA4(d, a, b0, b1) \
    asm volatile("mma.sync.aligned.m16n8k16.row.col.f32.f16.f16.f32 " \
        "{%0,%1,%2,%3}, {%4,%5,%6,%7}, {%8,%9}, {%0,%1,%2,%3};" \
        : "+f"((d)[0]), "+f"((d)[1]), "+f"((d)[2]), "+f"((d)[3]) \
        : "r"((a)[0]), "r"((a)[1]), "r"((a)[2]), "r"((a)[3]), "r"(b0), "r"(b1))

// compute 4 weights (2 pixel-pairs) for one bin and store as one STS.64
// One MUFU rcp per pair: r = rcp(q0*q1); w0 = (y0*q1)*r; w1 = (y1*q0)*r.
__device__ __forceinline__ void gen_duo(
    const float* S, const float* siy, int px, float ck, uint32_t sts_addr)
{
    float4 sv = *(const float4*)(S + px);
    float4 yv = *(const float4*)(siy + px);
    float d0 = sv.x - ck, d1 = sv.y - ck, d2 = sv.z - ck, d3 = sv.w - ck;
    float q0 = fmaf(d0, d0, A2), q1 = fmaf(d1, d1, A2);
    float q2 = fmaf(d2, d2, A2), q3 = fmaf(d3, d3, A2);
    float rA = frcp(q0 * q1);
    float rB = frcp(q2 * q3);
    float w0 = (yv.x * q1) * rA, w1 = (yv.y * q0) * rA;
    float w2 = (yv.z * q3) * rB, w3 = (yv.w * q2) * rB;
    uint32_t pk0, pk1;
    asm("cvt.rn.f16x2.f32 %0, %1, %2;" : "=r"(pk0) : "f"(w1), "f"(w0));
    asm("cvt.rn.f16x2.f32 %0, %1, %2;" : "=r"(pk1) : "f"(w3), "f"(w2));
    STS64(sts_addr, pk0, pk1);
}

// =====================================================================
// weight generation for one 64-px stage into buffer wb
// thread role: g = t>>6 (0..3), k = t&63.
//   g 0..2: matrix j=g, bin k, pair-duos covering pairs 0..23 (px 0..47)
//   g 3   : all 3 matrices, bin k, pair-duos covering pairs 24..31 (px 48..63)
// even rotation by k>>3 spreads duos so 16-lane STS.64 phases are
// conflict-free (rot classes {0,6},{12,18} -> disjoint mod-4 banks).
// =====================================================================
__device__ __forceinline__ void gen_stage(
    int st, uint32_t wb, const float* s1, const float* s2, const float* s3,
    const float* siy, int g, int k, float ck)
{
    const int sb = st * SPX;
    const uint32_t kxor = (uint32_t)(k & 7) << 4;
    if (g < 3) {
        const float* S = (g == 0) ? s1 : (g == 1 ? s2 : s3);
        const uint32_t rowa = wb + (uint32_t)g * 8192u + (uint32_t)k * 128u;
        const int rot = 6 * ((k >> 3) & 3);            // even
        #pragma unroll
        for (int pd = 0; pd < 12; pd++) {
            int ppr = 2 * pd + rot; if (ppr >= 24) ppr -= 24;   // even
            gen_duo(S, siy, sb + 2 * ppr, ck,
                    rowa + (((uint32_t)(4 * ppr)) ^ kxor));
        }
    } else {
        const int rot = 2 * ((k >> 3) & 3);            // even
        #pragma unroll
        for (int j = 0; j < 3; j++) {
            const float* S = (j == 0) ? s1 : (j == 1 ? s2 : s3);
            const uint32_t rowa = wb + (uint32_t)j * 8192u + (uint32_t)k * 128u;
            #pragma unroll
            for (int pq = 0; pq < 4; pq++) {
                const int ppr = 24 + ((2 * pq + rot) & 7);      // even, 24..30
                gen_duo(S, siy, sb + 2 * ppr, ck,
                        rowa + (((uint32_t)(4 * ppr)) ^ kxor));
            }
        }
    }
}

// =====================================================================
// K1: tensor-core histogram. Per block: (img,batch) x 512-px chunk.
//   a_j[k][px] = SCALE*sqrt(iy)*A2*rcp((d_j-c_k)^2+A2)  (fp16)
//   H_r = a1*a2^T; H_g[u,v] = (a1*a3^T)[63-u, v]; H_b[u,v] = (a2*a3^T)[63-u,63-v]
// =====================================================================
__global__ void __launch_bounds__(256, 2) hist_kernel(const float* __restrict__ x,
                                                      const float* __restrict__ y) {
    extern __shared__ __align__(16) unsigned char smem_raw[];
    float* s1  = (float*)smem_raw;
    float* s2  = s1 + KPIX;
    float* s3  = s2 + KPIX;
    float* siy = s3 + KPIX;
    const uint32_t smb = smem_u32(smem_raw);

    const int t  = threadIdx.x;
    const int bx = blockIdx.x;
    const int ib    = bx >> 7;               // 0..15
    const int chunk = bx & (NCH - 1);
    const float* base = (ib < 8 ? x : y) + (size_t)(ib & 7) * 3 * NPIX + chunk * KPIX;

    // ---- prep: chroma diffs + scaled sqrt-intensity ----
    {
        const int p = 2 * t;
        float2 c0 = *(const float2*)(base + p);
        float2 c1 = *(const float2*)(base + NPIX + p);
        float2 c2 = *(const float2*)(base + 2 * NPIX + p);
        float a0[2] = {c0.x, c0.y}, a1[2] = {c1.x, c1.y}, a2v[2] = {c2.x, c2.y};
        #pragma unroll
        for (int j = 0; j < 2; j++) {
            float v0 = a0[j] + EPSf, v1 = a1[j] + EPSf, v2 = a2v[j] + EPSf;
            float l0 = __logf(v0), l1 = __logf(v1), l2 = __logf(v2);
            s1[p + j] = l0 - l1;             // d1 = lr - lg
            s2[p + j] = l0 - l2;             // d2 = lr - lb
            s3[p + j] = l1 - l2;             // d3 = lg - lb
            float ss = fmaf(v0, v0, fmaf(v1, v1, v2 * v2));
            siy[p + j] = (SCALE * A2) * sqrtf(sqrtf(ss));   // SCALE*sqrt(iy)*A2
        }
    }

    // gen role
    const int g = t >> 6, k = t & 63;
    const float ck = fmaf((float)k, Hstep, LOf);

    // mma role: warp w -> rows [mr,mr+16), cols [nc,nc+32)
    const int w = t >> 5, lane = t & 31;
    const int mr = 16 * (w >> 1), nc = 32 * (w & 1);
    const int rr = lane & 7;
    const uint32_t arow = (uint32_t)(mr + rr + 8 * ((lane >> 3) & 1)) * 128u;
    const uint32_t akh  = (uint32_t)(lane >> 4) * 16u;
    const uint32_t brow = (uint32_t)(nc + rr + 8 * (lane >> 4)) * 128u;
    const uint32_t bkh  = (uint32_t)((lane >> 3) & 1) * 16u;
    const uint32_t sxor = (uint32_t)rr << 4;

    float ar[16] = {}, ag[16] = {}, ab[16] = {};

    __syncthreads();
    gen_stage(0, smb + W_OFF, s1, s2, s3, siy, g, k, ck);
    __syncthreads();

    for (int st = 0; st < NSTG; st++) {
        const uint32_t wb = smb + W_OFF + (uint32_t)(st & 1) * W_BUFSTR;
        if (st + 1 < NSTG)
            gen_stage(st + 1, smb + W_OFF + (uint32_t)((st & 1) ^ 1) * W_BUFSTR,
                      s1, s2, s3, siy, g, k, ck);

        const uint32_t w1b = wb, w2b = wb + 8192u, w3b = wb + 16384u;
        #pragma unroll
        for (int ks = 0; ks < 4; ks++) {
            const uint32_t offA = (32u * ks + akh) ^ sxor;
            const uint32_t offB = (32u * ks + bkh) ^ sxor;
            uint32_t A1[4], A2r[4], B2[8], B3[8];
            LDSM4(A1[0], A1[1], A1[2], A1[3],   w1b + arow + offA);
            LDSM4(A2r[0], A2r[1], A2r[2], A2r[3], w2b + arow + offA);
            LDSM4(B2[0], B2[1], B2[2], B2[3],   w2b + brow + offB);
            LDSM4(B2[4], B2[5], B2[6], B2[7],   w2b + brow + 2048u + offB);
            LDSM4(B3[0], B3[1], B3[2], B3[3],   w3b + brow + offB);
            LDSM4(B3[4], B3[5], B3[6], B3[7],   w3b + brow + 2048u + offB);
            #pragma unroll
            for (int j = 0; j < 4; j++) {
                MMA4(ar + 4 * j, A1,  B2[2 * j], B2[2 * j + 1]);
                MMA4(ag + 4 * j, A1,  B3[2 * j], B3[2 * j + 1]);
                MMA4(ab + 4 * j, A2r, B3[2 * j], B3[2 * j + 1]);
            }
        }
        __syncthreads();
    }

    // ---- epilogue: store with channel bin-reversal folded in ----
    float* op = g_partial[bx];
    const int r = lane >> 2, c = 2 * (lane & 3);
    #pragma unroll
    for (int j = 0; j < 4; j++) {
        const int col = nc + 8 * j + c;
        const int u0 = mr + r, u1 = u0 + 8;
        *(float2*)&op[u0 * 64 + col] = make_float2(ar[4 * j],     ar[4 * j + 1]);
        *(float2*)&op[u1 * 64 + col] = make_float2(ar[4 * j + 2], ar[4 * j + 3]);
        *(float2*)&op[4096 + (63 - u0) * 64 + col] = make_float2(ag[4 * j],     ag[4 * j + 1]);
        *(float2*)&op[4096 + (63 - u1) * 64 + col] = make_float2(ag[4 * j + 2], ag[4 * j + 3]);
        *(float2*)&op[8192 + (63 - u0) * 64 + (62 - col)] = make_float2(ab[4 * j + 1], ab[4 * j]);
        *(float2*)&op[8192 + (63 - u1) * 64 + (62 - col)] = make_float2(ab[4 * j + 3], ab[4 * j + 2]);
    }
}

// =====================================================================
// K2: reduce 128 chunk partials per (img,batch)
// =====================================================================
__global__ void __launch_bounds__(256) reduce_kernel() {
    const int ib  = blockIdx.x / 24;
    const int seg = blockIdx.x % 24;
    const int e0  = seg * 512;
    for (int e = e0 + threadIdx.x; e < e0 + 512; e += 256) {
        float s = 0.0f;
        #pragma unroll 8
        for (int c = 0; c < NCH; c++)
            s += g_partial[ib * NCH + c][e];
        g_hist[ib][e] = s;
    }
}

// =====================================================================
// K3: per-batch totals + Hellinger-style distance
// =====================================================================
__global__ void __launch_bounds__(256) loss_kernel() {
    const int b = blockIdx.x;
    const int t = threadIdx.x;
    __shared__ float rx[256], ry[256];

    float sx = 0.0f, sy = 0.0f;
    for (int e = t; e < 3 * 4096; e += 256) {
        sx += g_hist[b][e];
        sy += g_hist[8 + b][e];
    }
    rx[t] = sx; ry[t] = sy;
    __syncthreads();
    for (int s2 = 128; s2 > 0; s2 >>= 1) {
        if (t < s2) { rx[t] += rx[t + s2]; ry[t] += ry[t + s2]; }
        __syncthreads();
    }
    const float itx = 1.0f / rx[0];
    const float ity = 1.0f / ry[0];
    __syncthreads();

    float hs = 0.0f;
    for (int e = t; e < 3 * 4096; e += 256) {
        float d = sqrtf(g_hist[8 + b][e] * ity) - sqrtf(g_hist[b][e] * itx);
        hs = fmaf(d, d, hs);
    }
    rx[t] = hs;
    __syncthreads();
    for (int s2 = 128; s2 > 0; s2 >>= 1) {
        if (t < s2) rx[t] += rx[t + s2];
        __syncthreads();
    }
    if (t == 0) g_hb[b] = rx[0];
}

// =====================================================================
// K4: final scalar — mean over batch of sqrt(0.5 * h_b)
// =====================================================================
__global__ void final_kernel(float* __restrict__ out) {
    if (threadIdx.x == 0) {
        float s = 0.0f;
        for (int b = 0; b < 8; b++)
            s += sqrtf(g_hb[b] * 0.5f);
        out[0] = s * 0.125f;
    }
}

// =====================================================================
extern "C" void kernel_launch(void* const* d_in, const int* in_sizes, int n_in,
                              void* d_out, int out_size) {
    const float* x = (const float*)d_in[0];
    const float* y = (const float*)d_in[1];

    cudaFuncSetAttribute(hist_kernel, cudaFuncAttributeMaxDynamicSharedMemorySize, SMEM_SZ);
    hist_kernel<<<NBLK, 256, SMEM_SZ>>>(x, y);
    reduce_kernel<<<NIB * 24, 256>>>();
    loss_kernel<<<8, 256>>>();
    final_kernel<<<1, 32>>>((float*)d_out);
}